// round 3
// baseline (speedup 1.0000x reference)
#include <cuda_runtime.h>
#include <math_constants.h>

// ----------------------------------------------------------------------------
// Window VQ: argmin_k ||z - c_k||^2 == argmax_k ( z.c_k - 0.5*||c_k||^2 )
// Exact fp32 via packed fma.rn.f32x2 (FFMA2).
//
// R3: A stored PRE-DUPLICATED in smem ({a,a} pairs) so FFMA2 operands come
// straight from LDS (no mov.b64 duplication); 2 CTAs/SM (launch_bounds(256,2),
// <=128 regs) for 4 warps/SMSP latency hiding; BK=8 double-buffered B.
// Block tile 64m x 256n, thread tile 8x8.
// ----------------------------------------------------------------------------

#define D       128
#define BM      64
#define BNT     256
#define BK      8
#define NTHR    256

__device__ float g_cnorm[4096];

__global__ void cnorm_kernel(const float* __restrict__ cb, int K) {
    int row  = blockIdx.x * 8 + (threadIdx.x >> 5);
    int lane = threadIdx.x & 31;
    if (row < K) {
        const float4 v = reinterpret_cast<const float4*>(cb + (size_t)row * D)[lane];
        float s = v.x * v.x + v.y * v.y + v.z * v.z + v.w * v.w;
        #pragma unroll
        for (int o = 16; o; o >>= 1) s += __shfl_xor_sync(0xffffffffu, s, o);
        if (lane == 0) g_cnorm[row] = 0.5f * s;
    }
}

#define FMA2(a, x, y) asm("fma.rn.f32x2 %0, %1, %2, %0;" : "+l"(a) : "l"(x), "l"(y))

__device__ __forceinline__ float u2f_lo(unsigned long long a) {
    return __uint_as_float((unsigned)(a & 0xffffffffull));
}
__device__ __forceinline__ float u2f_hi(unsigned long long a) {
    return __uint_as_float((unsigned)(a >> 32));
}

// ---------------------------------------------------------------------------
// Dynamic smem: As-dup 16384 f (64KB) | Bs 2x2048 f (16KB) | Cn 2048 f (8KB)
// ---------------------------------------------------------------------------
__global__ __launch_bounds__(NTHR, 2)
void vq_main_kernel(const float* __restrict__ ze,
                    const float* __restrict__ cb,
                    float* __restrict__ out,
                    int K) {
    extern __shared__ __align__(16) float sm[];
    float* As = sm;              // [k 0..127][m 0..63 duplicated pairs]
    float* Bs = sm + 16384;      // 2 buffers of [kk 0..7][n 0..255] swizzled
    float* Cn = sm + 16384 + 4096;

    const int tid  = threadIdx.x;
    const int lane = tid & 31;
    const int wgrp = tid >> 5;
    const int tn   = lane;       // n-quads: tn and tn+32
    const int tm2  = wgrp;       // m-quads: tm2 and tm2+8 (m: 4tm2..+3, 32+4tm2..+3)

    const float4* cb4 = reinterpret_cast<const float4*>(cb);

    // ---- stage A pre-duplicated: As[k*128 + m*2] = As[..+1] = ze[m][k] ----
    {
        const float4* zsrc = reinterpret_cast<const float4*>(ze) + (size_t)blockIdx.x * (BM * 32);
        const int m  = tid & 63;
        const int qb = (tid >> 6) * 8;
        float2* As2 = reinterpret_cast<float2*>(As);
        #pragma unroll
        for (int u = 0; u < 8; ++u) {
            const int kq = qb + u;
            const float4 v = __ldg(&zsrc[m * 32 + kq]);
            As2[(kq * 4 + 0) * 64 + m] = make_float2(v.x, v.x);
            As2[(kq * 4 + 1) * 64 + m] = make_float2(v.y, v.y);
            As2[(kq * 4 + 2) * 64 + m] = make_float2(v.z, v.z);
            As2[(kq * 4 + 3) * 64 + m] = make_float2(v.w, v.w);
        }
    }
    // ---- stage cnorm ----
    for (int i = tid; i < K; i += NTHR) Cn[i] = g_cnorm[i];

    // ---- prologue: stage B chunk 0 ----
    {
        #pragma unroll
        for (int j = 0; j < 2; ++j) {
            const float4 v = __ldg(&cb4[(size_t)tid * 32 + j]);
            #pragma unroll
            for (int ki = 0; ki < 4; ++ki) {
                const int kk  = j * 4 + ki;
                const int col = ((((tid >> 2) ^ kk) & 63) << 2) | (tid & 3);
                Bs[kk * 256 + col] = (&v.x)[ki];
            }
        }
    }
    __syncthreads();

    unsigned long long acc[8][4];
    #pragma unroll
    for (int i = 0; i < 8; ++i)
        #pragma unroll
        for (int p = 0; p < 4; ++p) acc[i][p] = 0ull;

    float best[8];
    int   bidx[8];
    #pragma unroll
    for (int i = 0; i < 8; ++i) { best[i] = -CUDART_INF_F; bidx[i] = 0; }

    const int nchunks = (K >> 8) * 16;   // 128 for K=2048
    for (int cc = 0; cc < nchunks; ++cc) {
        const float* Bbuf = Bs + (cc & 1) * 2048;
        const int kc = cc & 15;          // k-chunk within n-tile

        // prefetch next chunk (2 float4 = 8 regs)
        float4 vn0, vn1;
        const bool more = (cc + 1 < nchunks);
        if (more) {
            const int nt2 = (cc + 1) >> 4, kc2 = (cc + 1) & 15;
            const size_t base = ((size_t)nt2 * 256 + tid) * 32 + kc2 * 2;
            vn0 = __ldg(&cb4[base]);
            vn1 = __ldg(&cb4[base + 1]);
        }

        // ---- compute: 8 k-steps ----
        #pragma unroll
        for (int kk = 0; kk < BK; ++kk) {
            const int k = kc * 8 + kk;
            const float* Ak = As + (k << 7) + (tm2 << 3);
            const ulonglong2 a01 = *reinterpret_cast<const ulonglong2*>(Ak);
            const ulonglong2 a23 = *reinterpret_cast<const ulonglong2*>(Ak + 4);
            const ulonglong2 a45 = *reinterpret_cast<const ulonglong2*>(Ak + 64);
            const ulonglong2 a67 = *reinterpret_cast<const ulonglong2*>(Ak + 68);
            const int q = (tn ^ kk) & 63;
            const ulonglong2 b0 = *reinterpret_cast<const ulonglong2*>(&Bbuf[kk * 256 + (q << 2)]);
            const ulonglong2 b1 = *reinterpret_cast<const ulonglong2*>(&Bbuf[kk * 256 + 128 + (q << 2)]);
            FMA2(acc[0][0], a01.x, b0.x); FMA2(acc[0][1], a01.x, b0.y);
            FMA2(acc[0][2], a01.x, b1.x); FMA2(acc[0][3], a01.x, b1.y);
            FMA2(acc[1][0], a01.y, b0.x); FMA2(acc[1][1], a01.y, b0.y);
            FMA2(acc[1][2], a01.y, b1.x); FMA2(acc[1][3], a01.y, b1.y);
            FMA2(acc[2][0], a23.x, b0.x); FMA2(acc[2][1], a23.x, b0.y);
            FMA2(acc[2][2], a23.x, b1.x); FMA2(acc[2][3], a23.x, b1.y);
            FMA2(acc[3][0], a23.y, b0.x); FMA2(acc[3][1], a23.y, b0.y);
            FMA2(acc[3][2], a23.y, b1.x); FMA2(acc[3][3], a23.y, b1.y);
            FMA2(acc[4][0], a45.x, b0.x); FMA2(acc[4][1], a45.x, b0.y);
            FMA2(acc[4][2], a45.x, b1.x); FMA2(acc[4][3], a45.x, b1.y);
            FMA2(acc[5][0], a45.y, b0.x); FMA2(acc[5][1], a45.y, b0.y);
            FMA2(acc[5][2], a45.y, b1.x); FMA2(acc[5][3], a45.y, b1.y);
            FMA2(acc[6][0], a67.x, b0.x); FMA2(acc[6][1], a67.x, b0.y);
            FMA2(acc[6][2], a67.x, b1.x); FMA2(acc[6][3], a67.x, b1.y);
            FMA2(acc[7][0], a67.y, b0.x); FMA2(acc[7][1], a67.y, b0.y);
            FMA2(acc[7][2], a67.y, b1.x); FMA2(acc[7][3], a67.y, b1.y);
        }

        // ---- stage next chunk into other buffer ----
        if (more) {
            float* Bn = Bs + ((cc + 1) & 1) * 2048;
            #pragma unroll
            for (int ki = 0; ki < 4; ++ki) {
                const int c0 = ((((tid >> 2) ^ ki) & 63) << 2) | (tid & 3);
                const int c1 = ((((tid >> 2) ^ (4 + ki)) & 63) << 2) | (tid & 3);
                Bn[ki * 256 + c0]       = (&vn0.x)[ki];
                Bn[(4 + ki) * 256 + c1] = (&vn1.x)[ki];
            }
        }

        // ---- epilogue per n-tile: scores + running argmax ----
        if (kc == 15) {
            const int nbase = (cc >> 4) << 8;
            #pragma unroll
            for (int i = 0; i < 8; ++i) {
                #pragma unroll
                for (int p = 0; p < 4; ++p) {
                    const int n0 = nbase + tn * 4 + ((p & 2) ? 128 : 0) + ((p & 1) << 1);
                    const float2 cn2 = *reinterpret_cast<const float2*>(&Cn[n0]);
                    const float s0 = u2f_lo(acc[i][p]) - cn2.x;
                    const float s1 = u2f_hi(acc[i][p]) - cn2.y;
                    if (s0 > best[i]) { best[i] = s0; bidx[i] = n0; }
                    if (s1 > best[i]) { best[i] = s1; bidx[i] = n0 + 1; }
                    acc[i][p] = 0ull;
                }
            }
        }
        __syncthreads();
    }

    // ---- cross-thread reduction: 32 candidates/window, alias onto As ----
    float* sred = As;                      // 64*32 floats
    int*   sidx = (int*)(As + 2048);       // 64*32 ints
    int*   widx = (int*)(As + 4096);       // 64 ints
    #pragma unroll
    for (int i = 0; i < 8; ++i) {
        const int m = (i < 4) ? (tm2 * 4 + i) : (32 + tm2 * 4 + (i - 4));
        sred[m * 32 + tn] = best[i];
        sidx[m * 32 + tn] = bidx[i];
    }
    __syncthreads();
    if (tid < 64) {
        float bs = sred[tid * 32];
        int   bi = sidx[tid * 32];
        #pragma unroll
        for (int q = 1; q < 32; ++q) {
            const float s  = sred[tid * 32 + q];
            const int   ix = sidx[tid * 32 + q];
            if (s > bs || (s == bs && ix < bi)) { bs = s; bi = ix; }
        }
        widx[tid] = bi;
    }
    __syncthreads();

    // ---- gather winning codebook rows (L2-hot) ----
    float4* out4 = reinterpret_cast<float4*>(out) + (size_t)blockIdx.x * (BM * 32);
    #pragma unroll
    for (int i = 0; i < 8; ++i) {
        const int f = i * 256 + tid;
        const int w = f >> 5, c = f & 31;
        out4[f] = __ldg(&cb4[(size_t)widx[w] * 32 + c]);
    }
}

// ---------------------------------------------------------------------------
extern "C" void kernel_launch(void* const* d_in, const int* in_sizes, int n_in,
                              void* d_out, int out_size) {
    const float* ze = (const float*)d_in[0];
    const float* cb = (const float*)d_in[1];
    float* out = (float*)d_out;

    const int M = in_sizes[0] / D;   // 65536
    const int K = in_sizes[1] / D;   // 2048

    const int smem_bytes = (16384 + 4096 + 2048) * (int)sizeof(float);   // 88 KB
    cudaFuncSetAttribute(vq_main_kernel, cudaFuncAttributeMaxDynamicSharedMemorySize,
                         smem_bytes);

    cnorm_kernel<<<(K + 7) / 8, NTHR>>>(cb, K);
    vq_main_kernel<<<M / BM, NTHR, smem_bytes>>>(ze, cb, out, K);
}

// round 4
// speedup vs baseline: 1.3745x; 1.3745x over previous
#include <cuda_runtime.h>
#include <math_constants.h>

// ----------------------------------------------------------------------------
// Window VQ: argmin_k ||z - c_k||^2 == argmax_k ( z.c_k - 0.5*||c_k||^2 )
// Exact fp32 via packed fma.rn.f32x2 (FFMA2).
//
// R4: codebook pre-transposed ONCE in global memory to k-major chunk layout
// so B staging is register-free cp.async (linear copy, no swizzle needed);
// m-pair accumulator packing (A = natural f32x2 broadcast from smem, only B
// duplicated: 4 dups/k-step); thread tile 16m x 4n; 2 CTAs/SM.
// ----------------------------------------------------------------------------

#define D       128
#define BM      64      // windows per block
#define BNT     256     // entries per n-tile
#define BK      32      // k per staged chunk
#define NTHR    256

__device__ float g_cnorm[4096];
__device__ __align__(16) float g_cbT[2048 * 128];   // transposed codebook, 1MB

// ---------------------------------------------------------------------------
__global__ void cnorm_kernel(const float* __restrict__ cb, int K) {
    int row  = blockIdx.x * 8 + (threadIdx.x >> 5);
    int lane = threadIdx.x & 31;
    if (row < K) {
        const float4 v = reinterpret_cast<const float4*>(cb + (size_t)row * D)[lane];
        float s = v.x * v.x + v.y * v.y + v.z * v.z + v.w * v.w;
        #pragma unroll
        for (int o = 16; o; o >>= 1) s += __shfl_xor_sync(0xffffffffu, s, o);
        if (lane == 0) g_cnorm[row] = 0.5f * s;
    }
}

// g_cbT layout: [tile nt][k 0..127][n 0..255]; chunk (nt,kc) = 32x256 floats
// contiguous = exactly what one cp.async staging pass copies.
__global__ void transpose_cb_kernel(const float* __restrict__ cb, int K) {
    const int o = blockIdx.x * NTHR + threadIdx.x;     // output float index
    if (o < K * D) {
        const int n  = o & 255;
        const int k  = (o >> 8) & 127;
        const int nt = o >> 15;
        g_cbT[o] = cb[((size_t)nt * 256 + n) * D + k];
    }
}

#define FMA2(a, x, y) asm("fma.rn.f32x2 %0, %1, %2, %0;" : "+l"(a) : "l"(x), "l"(y))
#define DUP64(d, f)   asm("mov.b64 %0, {%1, %1};" : "=l"(d) : "r"(__float_as_uint(f)))

__device__ __forceinline__ float u2f_lo(unsigned long long a) {
    return __uint_as_float((unsigned)(a & 0xffffffffull));
}
__device__ __forceinline__ float u2f_hi(unsigned long long a) {
    return __uint_as_float((unsigned)(a >> 32));
}

__device__ __forceinline__ void cp_async16(unsigned smem_addr, const float* gptr) {
    asm volatile("cp.async.cg.shared.global [%0], [%1], 16;"
                 :: "r"(smem_addr), "l"(gptr));
}

// ---------------------------------------------------------------------------
// Dynamic smem: As 8192 f (32KB) | Bs 2x8192 f (64KB) | Cn 2048 f (8KB) = 104KB
// ---------------------------------------------------------------------------
__global__ __launch_bounds__(NTHR, 2)
void vq_main_kernel(const float* __restrict__ ze,
                    const float* __restrict__ cb,
                    float* __restrict__ out,
                    int K) {
    extern __shared__ __align__(16) float sm[];
    float* As = sm;                       // [k 0..127][m 0..63]
    float* Bs = sm + 8192;                // 2 x [kk 0..31][n 0..255]
    float* Cn = sm + 8192 + 16384;

    const int tid = threadIdx.x;
    const int tm  = tid >> 6;             // 0..3 : m = tm*16 .. +15
    const int tn  = tid & 63;             // n-quad: n = 4*tn .. +3 per tile

    // ---- stage A transposed: As[k*64 + m] = ze[m][k] ----
    {
        const float4* zsrc = reinterpret_cast<const float4*>(ze) + (size_t)blockIdx.x * (BM * 32);
        const int m  = tid & 63;
        const int qb = (tid >> 6) * 8;
        #pragma unroll
        for (int u = 0; u < 8; ++u) {
            const int kq = qb + u;
            const float4 v = __ldg(&zsrc[m * 32 + kq]);
            As[(kq * 4 + 0) * 64 + m] = v.x;
            As[(kq * 4 + 1) * 64 + m] = v.y;
            As[(kq * 4 + 2) * 64 + m] = v.z;
            As[(kq * 4 + 3) * 64 + m] = v.w;
        }
    }
    for (int i = tid; i < K; i += NTHR) Cn[i] = g_cnorm[i];

    const unsigned bs_base = (unsigned)__cvta_generic_to_shared(Bs);

    // ---- prologue: stage chunk 0 via cp.async ----
    #pragma unroll
    for (int u = 0; u < 8; ++u) {
        const int off = u * 1024 + tid * 4;            // floats
        cp_async16(bs_base + off * 4, g_cbT + off);
    }
    asm volatile("cp.async.commit_group;");
    asm volatile("cp.async.wait_group 0;");
    __syncthreads();

    unsigned long long acc[8][4];
    #pragma unroll
    for (int i = 0; i < 8; ++i)
        #pragma unroll
        for (int j = 0; j < 4; ++j) acc[i][j] = 0ull;

    float best[16];
    int   bidx[16];
    #pragma unroll
    for (int i = 0; i < 16; ++i) { best[i] = -CUDART_INF_F; bidx[i] = 0; }

    const int nchunks = (K >> 8) * 4;     // 32 for K=2048
    for (int cc = 0; cc < nchunks; ++cc) {
        // issue next chunk's cp.async into the other buffer
        if (cc + 1 < nchunks) {
            const unsigned dst = bs_base + (((cc + 1) & 1) ? 8192u * 4u : 0u);
            const float* src = g_cbT + (size_t)(cc + 1) * 8192;
            #pragma unroll
            for (int u = 0; u < 8; ++u) {
                const int off = u * 1024 + tid * 4;
                cp_async16(dst + off * 4, src + off);
            }
            asm volatile("cp.async.commit_group;");
        }

        const float* Bbuf = Bs + (cc & 1) * 8192;
        const int kc = cc & 3;

        // ---- compute: 32 k-steps ----
        #pragma unroll 8
        for (int kk = 0; kk < BK; ++kk) {
            const int k = kc * 32 + kk;
            const float* Ak = As + (k << 6) + (tm << 4);
            const ulonglong2 p01 = *reinterpret_cast<const ulonglong2*>(Ak);      // m-pairs 0,1
            const ulonglong2 p23 = *reinterpret_cast<const ulonglong2*>(Ak + 4);  // 2,3
            const ulonglong2 p45 = *reinterpret_cast<const ulonglong2*>(Ak + 8);  // 4,5
            const ulonglong2 p67 = *reinterpret_cast<const ulonglong2*>(Ak + 12); // 6,7
            const float4 bq = *reinterpret_cast<const float4*>(&Bbuf[kk * 256 + (tn << 2)]);
            unsigned long long b0, b1, b2, b3;
            DUP64(b0, bq.x); DUP64(b1, bq.y); DUP64(b2, bq.z); DUP64(b3, bq.w);
            FMA2(acc[0][0], p01.x, b0); FMA2(acc[0][1], p01.x, b1);
            FMA2(acc[0][2], p01.x, b2); FMA2(acc[0][3], p01.x, b3);
            FMA2(acc[1][0], p01.y, b0); FMA2(acc[1][1], p01.y, b1);
            FMA2(acc[1][2], p01.y, b2); FMA2(acc[1][3], p01.y, b3);
            FMA2(acc[2][0], p23.x, b0); FMA2(acc[2][1], p23.x, b1);
            FMA2(acc[2][2], p23.x, b2); FMA2(acc[2][3], p23.x, b3);
            FMA2(acc[3][0], p23.y, b0); FMA2(acc[3][1], p23.y, b1);
            FMA2(acc[3][2], p23.y, b2); FMA2(acc[3][3], p23.y, b3);
            FMA2(acc[4][0], p45.x, b0); FMA2(acc[4][1], p45.x, b1);
            FMA2(acc[4][2], p45.x, b2); FMA2(acc[4][3], p45.x, b3);
            FMA2(acc[5][0], p45.y, b0); FMA2(acc[5][1], p45.y, b1);
            FMA2(acc[5][2], p45.y, b2); FMA2(acc[5][3], p45.y, b3);
            FMA2(acc[6][0], p67.x, b0); FMA2(acc[6][1], p67.x, b1);
            FMA2(acc[6][2], p67.x, b2); FMA2(acc[6][3], p67.x, b3);
            FMA2(acc[7][0], p67.y, b0); FMA2(acc[7][1], p67.y, b1);
            FMA2(acc[7][2], p67.y, b2); FMA2(acc[7][3], p67.y, b3);
        }

        // ---- epilogue per n-tile: scores + running argmax ----
        if (kc == 3) {
            const int nbase = (cc >> 2) << 8;
            const float4 cn4 = *reinterpret_cast<const float4*>(&Cn[nbase + (tn << 2)]);
            #pragma unroll
            for (int i = 0; i < 8; ++i) {
                #pragma unroll
                for (int j = 0; j < 4; ++j) {
                    const float cn = (&cn4.x)[j];
                    const int   n  = nbase + (tn << 2) + j;
                    const float s0 = u2f_lo(acc[i][j]) - cn;
                    const float s1 = u2f_hi(acc[i][j]) - cn;
                    if (s0 > best[2 * i])     { best[2 * i]     = s0; bidx[2 * i]     = n; }
                    if (s1 > best[2 * i + 1]) { best[2 * i + 1] = s1; bidx[2 * i + 1] = n; }
                    acc[i][j] = 0ull;
                }
            }
        }

        if (cc + 1 < nchunks) asm volatile("cp.async.wait_group 0;");
        __syncthreads();
    }

    // ---- cross-thread reduction: 64 candidates per window, alias onto Bs ----
    float* sred = Bs;                      // [m 0..63][cand 0..63]
    int*   sidx = (int*)(Bs + 4096);
    int*   widx = (int*)(Bs + 8192);
    #pragma unroll
    for (int i = 0; i < 16; ++i) {
        const int m = tm * 16 + i;
        sred[m * 64 + tn] = best[i];
        sidx[m * 64 + tn] = bidx[i];
    }
    __syncthreads();
    if (tid < 64) {
        float bs = sred[tid * 64];
        int   bi = sidx[tid * 64];
        #pragma unroll 8
        for (int q = 1; q < 64; ++q) {
            const float s  = sred[tid * 64 + q];
            const int   ix = sidx[tid * 64 + q];
            if (s > bs || (s == bs && ix < bi)) { bs = s; bi = ix; }
        }
        widx[tid] = bi;
    }
    __syncthreads();

    // ---- gather winning codebook rows (L2-hot) ----
    const float4* cb4  = reinterpret_cast<const float4*>(cb);
    float4*       out4 = reinterpret_cast<float4*>(out) + (size_t)blockIdx.x * (BM * 32);
    #pragma unroll
    for (int i = 0; i < 8; ++i) {
        const int f = i * 256 + tid;
        const int w = f >> 5, c = f & 31;
        out4[f] = __ldg(&cb4[(size_t)widx[w] * 32 + c]);
    }
}

// ---------------------------------------------------------------------------
extern "C" void kernel_launch(void* const* d_in, const int* in_sizes, int n_in,
                              void* d_out, int out_size) {
    const float* ze = (const float*)d_in[0];
    const float* cb = (const float*)d_in[1];
    float* out = (float*)d_out;

    const int M = in_sizes[0] / D;   // 65536
    const int K = in_sizes[1] / D;   // 2048

    const int smem_bytes = (8192 + 16384 + 2048) * (int)sizeof(float);   // 104 KB
    cudaFuncSetAttribute(vq_main_kernel, cudaFuncAttributeMaxDynamicSharedMemorySize,
                         smem_bytes);

    cnorm_kernel<<<(K + 7) / 8, NTHR>>>(cb, K);
    transpose_cb_kernel<<<(K * D + NTHR - 1) / NTHR, NTHR>>>(cb, K);
    vq_main_kernel<<<M / BM, NTHR, smem_bytes>>>(ze, cb, out, K);
}